// round 2
// baseline (speedup 1.0000x reference)
#include <cuda_runtime.h>

#define N_ROWS   100000
#define NBINS    512
#define BATCH    8192
#define KNN      16
#define COL_BLKS 64
#define ROWS_PER_COLBLK (BATCH / COL_BLKS)   // 128

// Scratch (no device allocs allowed) — written fully every launch, no zeroing needed.
__device__ float g_wpart[BATCH];             // w[i] * sum_j add[i][j]
__device__ float g_bpart[COL_BLKS * NBINS];  // per-strip column sums

// ---------------------------------------------------------------------------
// Kernel A: one CTA per batch row i. 16 warps, warp j handles neighbor j.
// add[i][j] = max_b( outputs[nn][b] + outputs[i][b] )
// ---------------------------------------------------------------------------
__global__ __launch_bounds__(512) void pair_kernel(
    const float* __restrict__ outputs,
    const float* __restrict__ y,
    const float* __restrict__ weights,
    float* __restrict__ out_boost)   // -> d_out + 3, length BATCH
{
    __shared__ float s_base[NBINS];
    __shared__ float s_add[KNN];

    const int i    = blockIdx.x;
    const int tid  = threadIdx.x;
    const int warp = tid >> 5;
    const int lane = tid & 31;

    // Stage base row in SMEM (128 x float4 = 512 floats)
    const float4* base4 = reinterpret_cast<const float4*>(outputs + (size_t)i * NBINS);
    float4* s4 = reinterpret_cast<float4*>(s_base);
    if (tid < NBINS / 4) s4[tid] = base4[tid];

    // Each warp: gather its neighbor row. Issue ALL global loads up front
    // (4 x LDG.128 per lane, independent) so the long-scoreboard waits overlap.
    const int nn = (int)y[i * KNN + warp];   // trunc of non-negative index
    const float4* nbr4 = reinterpret_cast<const float4*>(outputs + (size_t)nn * NBINS);

    float4 n0 = nbr4[lane];
    float4 n1 = nbr4[32 + lane];
    float4 n2 = nbr4[64 + lane];
    float4 n3 = nbr4[96 + lane];

    __syncthreads();   // s_base ready

    float4 b0 = s4[lane];
    float4 b1 = s4[32 + lane];
    float4 b2 = s4[64 + lane];
    float4 b3 = s4[96 + lane];

    float m0 = fmaxf(fmaxf(b0.x + n0.x, b0.y + n0.y), fmaxf(b0.z + n0.z, b0.w + n0.w));
    float m1 = fmaxf(fmaxf(b1.x + n1.x, b1.y + n1.y), fmaxf(b1.z + n1.z, b1.w + n1.w));
    float m2 = fmaxf(fmaxf(b2.x + n2.x, b2.y + n2.y), fmaxf(b2.z + n2.z, b2.w + n2.w));
    float m3 = fmaxf(fmaxf(b3.x + n3.x, b3.y + n3.y), fmaxf(b3.z + n3.z, b3.w + n3.w));
    float m  = fmaxf(fmaxf(m0, m1), fmaxf(m2, m3));

#pragma unroll
    for (int o = 16; o; o >>= 1)
        m = fmaxf(m, __shfl_xor_sync(0xffffffffu, m, o));
    if (lane == 0) s_add[warp] = m;
    __syncthreads();

    if (tid == 0) {
        float s = 0.f;
#pragma unroll
        for (int j = 0; j < KNN; j++) s += s_add[j];
        // booster = clip((2 - mean_j add)/2, min=0.5)
        out_boost[i] = fmaxf((2.0f - s * (1.0f / KNN)) * 0.5f, 0.5f);
        g_wpart[i]   = s * weights[i];
    }
}

// ---------------------------------------------------------------------------
// Kernel B: column sums of outputs[0:8192] in 64 row-strips (no atomics).
// ---------------------------------------------------------------------------
__global__ __launch_bounds__(NBINS) void colsum_kernel(const float* __restrict__ outputs)
{
    const int bin = threadIdx.x;   // 0..511, coalesced across bins
    const int blk = blockIdx.x;    // 0..63
    const float* p = outputs + (size_t)blk * ROWS_PER_COLBLK * NBINS + bin;
    float s = 0.f;
#pragma unroll 8
    for (int r = 0; r < ROWS_PER_COLBLK; r++) s += p[(size_t)r * NBINS];
    g_bpart[blk * NBINS + bin] = s;
}

// ---------------------------------------------------------------------------
// Kernel C: single CTA finalizer — b = max(col)-min(col), weighted mean, scalars.
// ---------------------------------------------------------------------------
__global__ __launch_bounds__(NBINS) void final_kernel(float* __restrict__ d_out)
{
    __shared__ float  s_max[NBINS];
    __shared__ float  s_min[NBINS];
    __shared__ double s_sum[NBINS];

    const int t = threadIdx.x;

    float col = 0.f;
#pragma unroll
    for (int b = 0; b < COL_BLKS; b++) col += g_bpart[b * NBINS + t];

    double ws = 0.0;
#pragma unroll
    for (int r = t; r < BATCH; r += NBINS) ws += (double)g_wpart[r];

    s_max[t] = col; s_min[t] = col; s_sum[t] = ws;
    __syncthreads();

    for (int o = NBINS / 2; o; o >>= 1) {
        if (t < o) {
            s_max[t] = fmaxf(s_max[t], s_max[t + o]);
            s_min[t] = fminf(s_min[t], s_min[t + o]);
            s_sum[t] += s_sum[t + o];
        }
        __syncthreads();
    }

    if (t == 0) {
        float bspread  = s_max[0] - s_min[0];
        float ratio    = bspread / ((float)N_ROWS / (float)NBINS);
        float add_mean = (float)(s_sum[0] / (double)(BATCH * KNN));
        float d        = 2.0f - add_mean;
        d = d * d;
        d_out[0] = ratio + d;   // cost
        d_out[1] = d;           // diff
        d_out[2] = ratio;       // b / target_b
    }
}

// ---------------------------------------------------------------------------
extern "C" void kernel_launch(void* const* d_in, const int* in_sizes, int n_in,
                              void* d_out, int out_size)
{
    const float* outputs = (const float*)d_in[0];  // (100000, 512) f32
    const float* y       = (const float*)d_in[1];  // (8192, 16)   f32 indices
    const float* weights = (const float*)d_in[2];  // (8192,)      f32
    float* out = (float*)d_out;                    // [cost, diff, ratio, boost(8192)]

    pair_kernel<<<BATCH, 512>>>(outputs, y, weights, out + 3);
    colsum_kernel<<<COL_BLKS, NBINS>>>(outputs);
    final_kernel<<<1, NBINS>>>(out);
}

// round 3
// speedup vs baseline: 1.0439x; 1.0439x over previous
#include <cuda_runtime.h>

#define N_ROWS   100000
#define NBINS    512
#define BATCH    8192
#define KNN      16
#define COL_BLKS 64
#define ROWS_PER_COLBLK 128
#define THREADS  256
#define TOTAL_BLKS (BATCH + COL_BLKS)

// Scratch (device allocs forbidden). Fully rewritten every launch.
__device__ float        g_wpart[BATCH];             // w[i] * sum_j add[i][j]
__device__ float        g_bpart[COL_BLKS * NBINS];  // per-strip column sums
__device__ unsigned int g_count = 0;                // ticket; reset by finalizer

__global__ __launch_bounds__(THREADS) void fused_kernel(
    const float* __restrict__ outputs,
    const float* __restrict__ y,
    const float* __restrict__ weights,
    float* __restrict__ d_out)
{
    __shared__ float    s_base[NBINS];
    __shared__ float    s_add[KNN];
    __shared__ unsigned s_ticket;
    __shared__ float    s_max[THREADS];
    __shared__ float    s_min[THREADS];
    __shared__ double   s_sum[THREADS];

    const int bid = blockIdx.x;
    const int tid = threadIdx.x;

    if (bid < COL_BLKS) {
        // ---- Column-sum strip (scheduled first so it overlaps the pair wave)
        const float* p = outputs + (size_t)bid * ROWS_PER_COLBLK * NBINS;
        float s0 = 0.f, s1 = 0.f;
#pragma unroll 4
        for (int r = 0; r < ROWS_PER_COLBLK; r++) {
            s0 += p[(size_t)r * NBINS + tid];
            s1 += p[(size_t)r * NBINS + tid + THREADS];
        }
        g_bpart[bid * NBINS + tid]           = s0;
        g_bpart[bid * NBINS + tid + THREADS] = s1;
    } else {
        // ---- Pair work for batch row i: 8 warps, each owns 2 neighbors.
        const int i    = bid - COL_BLKS;
        const int warp = tid >> 5;
        const int lane = tid & 31;

        // Stage base row (issue early; overlaps neighbor-load latency).
        const float4* base4 = reinterpret_cast<const float4*>(outputs + (size_t)i * NBINS);
        float4* s4 = reinterpret_cast<float4*>(s_base);
        if (tid < NBINS / 4) s4[tid] = base4[tid];

        const int j0  = warp * 2;
        const int nn0 = (int)y[i * KNN + j0];
        const int nn1 = (int)y[i * KNN + j0 + 1];
        const float4* p0 = reinterpret_cast<const float4*>(outputs + (size_t)nn0 * NBINS);
        const float4* p1 = reinterpret_cast<const float4*>(outputs + (size_t)nn1 * NBINS);

        // 8 independent LDG.128 per lane — all in flight before the barrier.
        float4 a0 = p0[lane], a1 = p0[32 + lane], a2 = p0[64 + lane], a3 = p0[96 + lane];
        float4 c0 = p1[lane], c1 = p1[32 + lane], c2 = p1[64 + lane], c3 = p1[96 + lane];

        __syncthreads();   // s_base ready

        float4 b0 = s4[lane], b1 = s4[32 + lane], b2 = s4[64 + lane], b3 = s4[96 + lane];

        float ma = fmaxf(
            fmaxf(fmaxf(fmaxf(b0.x + a0.x, b0.y + a0.y), fmaxf(b0.z + a0.z, b0.w + a0.w)),
                  fmaxf(fmaxf(b1.x + a1.x, b1.y + a1.y), fmaxf(b1.z + a1.z, b1.w + a1.w))),
            fmaxf(fmaxf(fmaxf(b2.x + a2.x, b2.y + a2.y), fmaxf(b2.z + a2.z, b2.w + a2.w)),
                  fmaxf(fmaxf(b3.x + a3.x, b3.y + a3.y), fmaxf(b3.z + a3.z, b3.w + a3.w))));
        float mb = fmaxf(
            fmaxf(fmaxf(fmaxf(b0.x + c0.x, b0.y + c0.y), fmaxf(b0.z + c0.z, b0.w + c0.w)),
                  fmaxf(fmaxf(b1.x + c1.x, b1.y + c1.y), fmaxf(b1.z + c1.z, b1.w + c1.w))),
            fmaxf(fmaxf(fmaxf(b2.x + c2.x, b2.y + c2.y), fmaxf(b2.z + c2.z, b2.w + c2.w)),
                  fmaxf(fmaxf(b3.x + c3.x, b3.y + c3.y), fmaxf(b3.z + c3.z, b3.w + c3.w))));

#pragma unroll
        for (int o = 16; o; o >>= 1) {
            ma = fmaxf(ma, __shfl_xor_sync(0xffffffffu, ma, o));
            mb = fmaxf(mb, __shfl_xor_sync(0xffffffffu, mb, o));
        }
        if (lane == 0) { s_add[j0] = ma; s_add[j0 + 1] = mb; }
        __syncthreads();

        if (tid == 0) {
            float s = 0.f;
#pragma unroll
            for (int j = 0; j < KNN; j++) s += s_add[j];
            d_out[3 + i] = fmaxf((2.0f - s * (1.0f / KNN)) * 0.5f, 0.5f);  // booster
            g_wpart[i]   = s * weights[i];
        }
    }

    // ---- Ticket: last CTA finalizes in-kernel (no extra launches).
    __threadfence();
    if (tid == 0) s_ticket = atomicAdd(&g_count, 1u);
    __syncthreads();
    if (s_ticket == TOTAL_BLKS - 1) {
        __threadfence();   // acquire side

        // Column totals: thread t owns columns t and t+256.
        float col0 = 0.f, col1 = 0.f;
#pragma unroll 8
        for (int b = 0; b < COL_BLKS; b++) {
            col0 += __ldcg(&g_bpart[b * NBINS + tid]);
            col1 += __ldcg(&g_bpart[b * NBINS + tid + THREADS]);
        }
        float mx = fmaxf(col0, col1);
        float mn = fminf(col0, col1);

        // Weighted-sum reduction (double accumulation, fixed order).
        double ws = 0.0;
#pragma unroll 8
        for (int r = tid; r < BATCH; r += THREADS) ws += (double)__ldcg(&g_wpart[r]);

        s_max[tid] = mx; s_min[tid] = mn; s_sum[tid] = ws;
        __syncthreads();
        for (int o = THREADS / 2; o; o >>= 1) {
            if (tid < o) {
                s_max[tid] = fmaxf(s_max[tid], s_max[tid + o]);
                s_min[tid] = fminf(s_min[tid], s_min[tid + o]);
                s_sum[tid] += s_sum[tid + o];
            }
            __syncthreads();
        }

        if (tid == 0) {
            float bspread  = s_max[0] - s_min[0];
            float ratio    = bspread / ((float)N_ROWS / (float)NBINS);
            float add_mean = (float)(s_sum[0] / (double)(BATCH * KNN));
            float d        = 2.0f - add_mean;
            d = d * d;
            d_out[0] = ratio + d;   // cost
            d_out[1] = d;           // diff
            d_out[2] = ratio;       // b / target_b
            g_count  = 0;           // reset for next graph replay
        }
    }
}

extern "C" void kernel_launch(void* const* d_in, const int* in_sizes, int n_in,
                              void* d_out, int out_size)
{
    const float* outputs = (const float*)d_in[0];  // (100000, 512) f32
    const float* y       = (const float*)d_in[1];  // (8192, 16)   f32 indices
    const float* weights = (const float*)d_in[2];  // (8192,)      f32
    float* out = (float*)d_out;                    // [cost, diff, ratio, boost(8192)]

    fused_kernel<<<TOTAL_BLKS, THREADS>>>(outputs, y, weights, out);
}